// round 1
// baseline (speedup 1.0000x reference)
#include <cuda_runtime.h>

// Problem constants (fixed by setup_inputs): B=8, L=K=2048, D=32, SIGMA=1, EPS=1, 10 iters.
#define BB 8
#define NN 2048
#define DD 32
#define TOT (BB * NN)
#define MAT_ELEMS ((size_t)BB * NN * NN)

// ---------------- device scratch (no runtime allocation allowed) ----------------
static __device__ float g_Hxx[MAT_ELEMS];   // exp(gauss(x_l, x_k))
static __device__ float g_Hyx[MAT_ELEMS];   // exp(gauss(y_k, x_l)), rows = y index
static __device__ float g_Hyy[MAT_ELEMS];   // exp(gauss(y_k, y_j))
static __device__ float g_nx[TOT], g_ny[TOT];
static __device__ float g_fxx[TOT], g_fyx[TOT], g_fxy[TOT], g_fyy[TOT];
static __device__ float g_w[TOT];
static __device__ float g_S0[TOT], g_S1[TOT], g_S2[TOT], g_S3[TOT];

__device__ __forceinline__ float* f_ptr(int s) {
    return s == 0 ? g_fxx : s == 1 ? g_fyx : s == 2 ? g_fxy : g_fyy;
}
__device__ __forceinline__ float* S_ptr(int s) {
    return s == 0 ? g_S0 : s == 1 ? g_S1 : s == 2 ? g_S2 : g_S3;
}
__device__ __forceinline__ const float* H_ptr(int s) {
    return s == 0 ? g_Hxx : s == 1 ? g_Hyx : g_Hyy;
}

// e^t for t in [0,1]: degree-9 Taylor (Horner). Max rel err ~1e-7.
// Replaces one MUFU.EX2 per matrix element with FMAs (FMA pipe is idle; MUFU is the bottleneck).
__device__ __forceinline__ float exp_unit(float t) {
    float p = 2.75573192e-6f;            // 1/9!
    p = fmaf(p, t, 2.48015873e-5f);      // 1/8!
    p = fmaf(p, t, 1.98412698e-4f);      // 1/7!
    p = fmaf(p, t, 1.38888889e-3f);      // 1/6!
    p = fmaf(p, t, 8.33333333e-3f);      // 1/5!
    p = fmaf(p, t, 4.16666667e-2f);      // 1/4!
    p = fmaf(p, t, 1.66666667e-1f);      // 1/3!
    p = fmaf(p, t, 0.5f);
    p = fmaf(p, t, 1.0f);
    p = fmaf(p, t, 1.0f);
    return p;
}

// ---------------- kernels ----------------

// Squared norms of x and y rows + zero-init potentials.
__global__ __launch_bounds__(256) void k_norms(const float* __restrict__ x,
                                               const float* __restrict__ y) {
    int i = blockIdx.x * 256 + threadIdx.x;
    if (i >= TOT) return;
    const float* xr = x + (size_t)i * DD;
    const float* yr = y + (size_t)i * DD;
    float sx = 0.f, sy = 0.f;
#pragma unroll
    for (int d = 0; d < DD; d++) {
        sx = fmaf(xr[d], xr[d], sx);
        sy = fmaf(yr[d], yr[d], sy);
    }
    g_nx[i] = sx;
    g_ny[i] = sy;
    g_fxx[i] = 0.f; g_fyx[i] = 0.f; g_fxy[i] = 0.f; g_fyy[i] = 0.f;
}

// Build H[b][r][c] = exp( exp( -max(nr+nc-2*dot, 0)/2 ) ).
// 64x64 tile per block, 256 threads, 4x4 register micro-tile, SMEM transposed ([d][row]).
__global__ __launch_bounds__(256) void k_build(int hsel,
                                               const float* __restrict__ Rm,
                                               const float* __restrict__ Cm,
                                               int rn, int cn) {
    __shared__ float srt[DD][68];   // [d][row], pad 68 -> 16B-aligned float4 reads
    __shared__ float sct[DD][68];
    int b = blockIdx.z;
    int r0 = blockIdx.y * 64, c0 = blockIdx.x * 64;
    const float* Rb = Rm + ((size_t)b * NN + r0) * DD;
    const float* Cb = Cm + ((size_t)b * NN + c0) * DD;
    for (int i = threadIdx.x; i < 64 * DD; i += 256) {
        int row = i >> 5, d = i & 31;
        srt[d][row] = Rb[i];
        sct[d][row] = Cb[i];
    }
    __syncthreads();

    int tx = threadIdx.x & 15, ty = threadIdx.x >> 4;
    float acc[4][4];
#pragma unroll
    for (int i = 0; i < 4; i++)
#pragma unroll
        for (int j = 0; j < 4; j++) acc[i][j] = 0.f;

#pragma unroll
    for (int d = 0; d < DD; d++) {
        float4 rv4 = *(const float4*)&srt[d][ty * 4];
        float4 cv4 = *(const float4*)&sct[d][tx * 4];
        float rv[4] = {rv4.x, rv4.y, rv4.z, rv4.w};
        float cv[4] = {cv4.x, cv4.y, cv4.z, cv4.w};
#pragma unroll
        for (int i = 0; i < 4; i++)
#pragma unroll
            for (int j = 0; j < 4; j++)
                acc[i][j] = fmaf(rv[i], cv[j], acc[i][j]);
    }

    const float* nRp = (rn ? g_ny : g_nx) + b * NN + r0;
    const float* nCp = (cn ? g_ny : g_nx) + b * NN + c0;
    float nr[4], ncv[4];
#pragma unroll
    for (int i = 0; i < 4; i++) nr[i] = nRp[ty * 4 + i];
#pragma unroll
    for (int j = 0; j < 4; j++) ncv[j] = nCp[tx * 4 + j];

    float* H = (hsel == 0 ? g_Hxx : hsel == 1 ? g_Hyx : g_Hyy);
#pragma unroll
    for (int i = 0; i < 4; i++) {
        float o[4];
#pragma unroll
        for (int j = 0; j < 4; j++) {
            float dist = nr[i] + ncv[j] - 2.f * acc[i][j];
            float t = __expf(-0.5f * fmaxf(dist, 0.f));   // gauss kernel value, t in (0,1]
            o[j] = exp_unit(t);                           // outer exp via polynomial
        }
        float4 o4 = make_float4(o[0], o[1], o[2], o[3]);
        *(float4*)&H[((size_t)b * NN + r0 + ty * 4 + i) * NN + c0 + tx * 4] = o4;
    }
}

// w[i] = exp(weight[i] + f[i]);  S[i] = 0 (needed by the transposed GEMV, harmless otherwise)
__global__ __launch_bounds__(256) void k_prep(const float* __restrict__ wt, int fsel, int ssel) {
    int i = blockIdx.x * 256 + threadIdx.x;
    if (i >= TOT) return;
    g_w[i] = __expf(wt[i] + f_ptr(fsel)[i]);
    S_ptr(ssel)[i] = 0.f;
}

// Row GEMV: one warp per row. S = sum_k H[row,k] * w[k].
// final_mode=0: fused epilogue f = 0.5 f - 0.5 log(S).  final_mode=1: store raw S.
__global__ __launch_bounds__(256) void k_gemv_rows(int hsel, int fsel, int ssel, int final_mode) {
    int gw = (blockIdx.x * 256 + threadIdx.x) >> 5;
    int lane = threadIdx.x & 31;
    if (gw >= TOT) return;
    int b = gw >> 11;
    const float4* hrow = (const float4*)(H_ptr(hsel) + (size_t)gw * NN);
    const float4* wv = (const float4*)(g_w + (b << 11));
    float acc0 = 0.f, acc1 = 0.f;
#pragma unroll
    for (int it = 0; it < 16; it += 2) {
        float4 h0 = hrow[it * 32 + lane];
        float4 w0 = wv[it * 32 + lane];
        float4 h1 = hrow[(it + 1) * 32 + lane];
        float4 w1 = wv[(it + 1) * 32 + lane];
        acc0 = fmaf(h0.x, w0.x, fmaf(h0.y, w0.y, fmaf(h0.z, w0.z, fmaf(h0.w, w0.w, acc0))));
        acc1 = fmaf(h1.x, w1.x, fmaf(h1.y, w1.y, fmaf(h1.z, w1.z, fmaf(h1.w, w1.w, acc1))));
    }
    float acc = acc0 + acc1;
#pragma unroll
    for (int o = 16; o; o >>= 1) acc += __shfl_xor_sync(0xffffffffu, acc, o);
    if (lane == 0) {
        if (final_mode) {
            S_ptr(ssel)[gw] = acc;
        } else {
            float* f = f_ptr(fsel);
            f[gw] = 0.5f * f[gw] - 0.5f * __logf(acc);
        }
    }
}

// Column GEMV over g_Hyx: S[l] += sum_k Hyx[b,k,l] * w[k].
// grid (KSPLIT=16, 2 col-chunks of 1024, B). Coalesced float4 row reads, atomic partial sums.
__global__ __launch_bounds__(256) void k_gemv_cols(int ssel) {
    __shared__ float ws[128];
    int b = blockIdx.z, lc = blockIdx.y, ks = blockIdx.x;
    int tid = threadIdx.x;
    if (tid < 128) ws[tid] = g_w[b * NN + ks * 128 + tid];
    __syncthreads();

    const float4* Hb = (const float4*)(g_Hyx + ((size_t)b * NN + ks * 128) * NN);
    int l4 = lc * 256 + tid;   // float4 column index in [0, 512)
    float4 acc = make_float4(0.f, 0.f, 0.f, 0.f);
#pragma unroll 8
    for (int k = 0; k < 128; k++) {
        float wk = ws[k];
        float4 h4 = Hb[(size_t)k * (NN / 4) + l4];
        acc.x = fmaf(h4.x, wk, acc.x);
        acc.y = fmaf(h4.y, wk, acc.y);
        acc.z = fmaf(h4.z, wk, acc.z);
        acc.w = fmaf(h4.w, wk, acc.w);
    }
    float* S = S_ptr(ssel) + b * NN + 4 * l4;
    atomicAdd(S + 0, acc.x);
    atomicAdd(S + 1, acc.y);
    atomicAdd(S + 2, acc.z);
    atomicAdd(S + 3, acc.w);
}

// Epilogue for the transposed update: f = 0.5 f - 0.5 log(S)
__global__ __launch_bounds__(256) void k_epi(int fsel, int ssel) {
    int i = blockIdx.x * 256 + threadIdx.x;
    if (i >= TOT) return;
    float* f = f_ptr(fsel);
    f[i] = 0.5f * f[i] - 0.5f * __logf(S_ptr(ssel)[i]);
}

// res[b] = sum_l (fe_xy - fe_xx) * exp(a) + sum_k (fe_yx - fe_yy) * exp(b)
// with fe_* = -log(S_*). S0=xx, S1=yx, S2=xy, S3=yy.
__global__ __launch_bounds__(256) void k_reduce(const float* __restrict__ a,
                                                const float* __restrict__ bw,
                                                float* __restrict__ out) {
    int b = blockIdx.x;
    float acc = 0.f;
    for (int i = threadIdx.x; i < NN; i += 256) {
        int idx = b * NN + i;
        float fexx = -__logf(g_S0[idx]);
        float feyx = -__logf(g_S1[idx]);
        float fexy = -__logf(g_S2[idx]);
        float feyy = -__logf(g_S3[idx]);
        acc += (fexy - fexx) * __expf(a[idx]) + (feyx - feyy) * __expf(bw[idx]);
    }
    __shared__ float red[256];
    red[threadIdx.x] = acc;
    __syncthreads();
    for (int s = 128; s; s >>= 1) {
        if (threadIdx.x < s) red[threadIdx.x] += red[threadIdx.x + s];
        __syncthreads();
    }
    if (threadIdx.x == 0) out[b] = red[0];   // EPSILON = 1
}

// ---------------- launch ----------------
extern "C" void kernel_launch(void* const* d_in, const int* in_sizes, int n_in,
                              void* d_out, int out_size) {
    const float* x = (const float*)d_in[0];   // (8, 2048, 32)
    const float* a = (const float*)d_in[1];   // (8, 2048)
    const float* y = (const float*)d_in[2];   // (8, 2048, 32)
    const float* b = (const float*)d_in[3];   // (8, 2048)
    float* out = (float*)d_out;               // (8,)

    const int SMALL_BLOCKS = TOT / 256;           // 64
    const int GEMV_BLOCKS = (TOT * 32) / 256;     // one warp/row -> 2048 blocks
    dim3 buildGrid(NN / 64, NN / 64, BB);         // (32, 32, 8)
    dim3 colsGrid(16, 2, BB);                     // k-split 16, 2 column chunks, batch

    // norms + zero potentials
    k_norms<<<SMALL_BLOCKS, 256>>>(x, y);

    // precompute exp(kernel) matrices
    k_build<<<buildGrid, 256>>>(0, x, x, 0, 0);   // Hxx
    k_build<<<buildGrid, 256>>>(1, y, x, 1, 0);   // Hyx (rows=y, cols=x)
    k_build<<<buildGrid, 256>>>(2, y, y, 1, 1);   // Hyy

    // 10 Gauss-Seidel Sinkhorn iterations
    for (int it = 0; it < 10; it++) {
        // fxx: LSE_k( Hxx[l,k] * exp(a_k + fxx_k) )
        k_prep<<<SMALL_BLOCKS, 256>>>(a, 0, 0);
        k_gemv_rows<<<GEMV_BLOCKS, 256>>>(0, 0, 0, 0);
        // fyx: uses OLD fxy: LSE_l( Hyx[k,l] * exp(a_l + fxy_l) )
        k_prep<<<SMALL_BLOCKS, 256>>>(a, 2, 1);
        k_gemv_rows<<<GEMV_BLOCKS, 256>>>(1, 1, 1, 0);
        // fxy: uses NEW fyx: LSE_k( Hyx[k,l] * exp(b_k + fyx_k) ) (transposed)
        k_prep<<<SMALL_BLOCKS, 256>>>(b, 1, 2);
        k_gemv_cols<<<colsGrid, 256>>>(2);
        k_epi<<<SMALL_BLOCKS, 256>>>(2, 2);
        // fyy: LSE_j( Hyy[k,j] * exp(b_j + fyy_j) )
        k_prep<<<SMALL_BLOCKS, 256>>>(b, 3, 3);
        k_gemv_rows<<<GEMV_BLOCKS, 256>>>(2, 3, 3, 0);
    }

    // final extrapolation: raw sums S0..S3
    k_prep<<<SMALL_BLOCKS, 256>>>(a, 0, 0);       // w = exp(a + fxx)
    k_gemv_rows<<<GEMV_BLOCKS, 256>>>(0, 0, 0, 1);
    k_prep<<<SMALL_BLOCKS, 256>>>(a, 2, 1);       // w = exp(a + fxy)
    k_gemv_rows<<<GEMV_BLOCKS, 256>>>(1, 0, 1, 1);
    k_prep<<<SMALL_BLOCKS, 256>>>(b, 1, 2);       // w = exp(b + fyx), zeroes S2
    k_gemv_cols<<<colsGrid, 256>>>(2);
    k_prep<<<SMALL_BLOCKS, 256>>>(b, 3, 3);       // w = exp(b + fyy)
    k_gemv_rows<<<GEMV_BLOCKS, 256>>>(2, 0, 3, 1);

    k_reduce<<<BB, 256>>>(a, b, out);
}

// round 2
// speedup vs baseline: 1.6489x; 1.6489x over previous
#include <cuda_runtime.h>
#include <cuda_fp16.h>

// Problem constants (fixed by setup_inputs): B=8, L=K=2048, D=32, SIGMA=1, EPS=1, 10 iters.
#define BB 8
#define NN 2048
#define DD 32
#define TOT (BB * NN)
#define MAT_ELEMS ((size_t)BB * NN * NN)

// ---------------- device scratch (no runtime allocation allowed) ----------------
static __device__ __half g_Hxx[MAT_ELEMS];   // exp(gauss(x_l, x_k)) in fp16
static __device__ __half g_Hyx[MAT_ELEMS];   // exp(gauss(y_k, x_l)), rows = y index
static __device__ __half g_Hyy[MAT_ELEMS];   // exp(gauss(y_k, y_j))
static __device__ float g_nx[TOT], g_ny[TOT];
static __device__ float g_fxx[TOT], g_fyx[TOT], g_fxy[TOT], g_fyy[TOT];
static __device__ float g_w0[TOT], g_w1[TOT], g_w2[TOT], g_w3[TOT];
static __device__ float g_S0[TOT], g_S1[TOT], g_S2[TOT], g_S3[TOT];

// sel mapping: 0 -> (Hxx, w0, fxx, S0), 1 -> (Hyx, w1, fyx, S1), 2 -> (Hyy, w3, fyy, S3)
__device__ __forceinline__ const __half* H_of(int s) {
    return s == 0 ? g_Hxx : s == 1 ? g_Hyx : g_Hyy;
}
__device__ __forceinline__ const float* w_of(int s) {
    return s == 0 ? g_w0 : s == 1 ? g_w1 : g_w3;
}
__device__ __forceinline__ float* f_of(int s) {
    return s == 0 ? g_fxx : s == 1 ? g_fyx : g_fyy;
}
__device__ __forceinline__ float* S_of(int s) {
    return s == 0 ? g_S0 : s == 1 ? g_S1 : g_S3;
}

// ---------------- kernels ----------------

// Squared norms of x and y rows + zero-init potentials.
__global__ __launch_bounds__(256) void k_norms(const float* __restrict__ x,
                                               const float* __restrict__ y) {
    int i = blockIdx.x * 256 + threadIdx.x;
    if (i >= TOT) return;
    const float* xr = x + (size_t)i * DD;
    const float* yr = y + (size_t)i * DD;
    float sx = 0.f, sy = 0.f;
#pragma unroll
    for (int d = 0; d < DD; d++) {
        sx = fmaf(xr[d], xr[d], sx);
        sy = fmaf(yr[d], yr[d], sy);
    }
    g_nx[i] = sx;
    g_ny[i] = sy;
    g_fxx[i] = 0.f; g_fyx[i] = 0.f; g_fxy[i] = 0.f; g_fyy[i] = 0.f;
}

// Build H[b][r][c] = exp( exp( -max(nr+nc-2*dot, 0)/2 ) ), stored fp16.
// 64x64 tile per block, 256 threads, 4x4 register micro-tile, SMEM transposed ([d][row]).
__global__ __launch_bounds__(256) void k_build(int hsel,
                                               const float* __restrict__ Rm,
                                               const float* __restrict__ Cm,
                                               int rn, int cn) {
    __shared__ float srt[DD][68];
    __shared__ float sct[DD][68];
    int b = blockIdx.z;
    int r0 = blockIdx.y * 64, c0 = blockIdx.x * 64;
    const float* Rb = Rm + ((size_t)b * NN + r0) * DD;
    const float* Cb = Cm + ((size_t)b * NN + c0) * DD;
    for (int i = threadIdx.x; i < 64 * DD; i += 256) {
        int row = i >> 5, d = i & 31;
        srt[d][row] = Rb[i];
        sct[d][row] = Cb[i];
    }
    __syncthreads();

    int tx = threadIdx.x & 15, ty = threadIdx.x >> 4;
    float acc[4][4];
#pragma unroll
    for (int i = 0; i < 4; i++)
#pragma unroll
        for (int j = 0; j < 4; j++) acc[i][j] = 0.f;

#pragma unroll
    for (int d = 0; d < DD; d++) {
        float4 rv4 = *(const float4*)&srt[d][ty * 4];
        float4 cv4 = *(const float4*)&sct[d][tx * 4];
        float rv[4] = {rv4.x, rv4.y, rv4.z, rv4.w};
        float cv[4] = {cv4.x, cv4.y, cv4.z, cv4.w};
#pragma unroll
        for (int i = 0; i < 4; i++)
#pragma unroll
            for (int j = 0; j < 4; j++)
                acc[i][j] = fmaf(rv[i], cv[j], acc[i][j]);
    }

    const float* nRp = (rn ? g_ny : g_nx) + b * NN + r0;
    const float* nCp = (cn ? g_ny : g_nx) + b * NN + c0;
    float nr[4], ncv[4];
#pragma unroll
    for (int i = 0; i < 4; i++) nr[i] = nRp[ty * 4 + i];
#pragma unroll
    for (int j = 0; j < 4; j++) ncv[j] = nCp[tx * 4 + j];

    __half* H = (hsel == 0 ? g_Hxx : hsel == 1 ? g_Hyx : g_Hyy);
#pragma unroll
    for (int i = 0; i < 4; i++) {
        float o[4];
#pragma unroll
        for (int j = 0; j < 4; j++) {
            float dist = nr[i] + ncv[j] - 2.f * acc[i][j];
            float t = __expf(-0.5f * fmaxf(dist, 0.f));   // gauss value, t in (0,1]
            o[j] = __expf(t);                             // outer exp (MUFU, FMA pipe is the bottleneck)
        }
        union { __half2 h2[2]; uint2 u; } cv;
        cv.h2[0] = __floats2half2_rn(o[0], o[1]);
        cv.h2[1] = __floats2half2_rn(o[2], o[3]);
        *(uint2*)&H[((size_t)b * NN + r0 + ty * 4 + i) * NN + c0 + tx * 4] = cv.u;
    }
}

// Per-iteration prep: optionally apply the deferred fxy epilogue (from previous
// iteration's column GEMV), then compute the three independent weight vectors.
__global__ __launch_bounds__(256) void k_prep_all(const float* __restrict__ a,
                                                  const float* __restrict__ bw,
                                                  int do_epi) {
    int i = blockIdx.x * 256 + threadIdx.x;
    if (i >= TOT) return;
    float fxy = g_fxy[i];
    if (do_epi) {
        fxy = 0.5f * fxy - 0.5f * __logf(g_S2[i]);
        g_fxy[i] = fxy;
    }
    g_w0[i] = __expf(a[i] + g_fxx[i]);   // for fxx update (Hxx rows)
    g_w1[i] = __expf(a[i] + fxy);        // for fyx update (Hyx rows, uses OLD fxy)
    g_w3[i] = __expf(bw[i] + g_fyy[i]);  // for fyy update (Hyy rows)
}

// prep for the column GEMV: w2 = exp(b + fyx_new), zero S2 accumulator.
__global__ __launch_bounds__(256) void k_prep2(const float* __restrict__ bw) {
    int i = blockIdx.x * 256 + threadIdx.x;
    if (i >= TOT) return;
    g_w2[i] = __expf(bw[i] + g_fyx[i]);
    g_S2[i] = 0.f;
}

// Row GEMV over one or two H matrices (selected by blockIdx.y -> sel0/sel1).
// One warp per row: S = sum_k H[row,k] * w[k] (fp16 H, fp32 w/accumulate).
// final_mode=0: f = 0.5 f - 0.5 log(S).  final_mode=1: store raw S.
__global__ __launch_bounds__(256) void k_gemv_rows(int sel0, int sel1, int final_mode) {
    int sel = blockIdx.y == 0 ? sel0 : sel1;
    int gw = (blockIdx.x * 256 + threadIdx.x) >> 5;
    int lane = threadIdx.x & 31;
    int b = gw >> 11;
    const uint4* hrow = (const uint4*)(H_of(sel) + (size_t)gw * NN);  // 8 halves per uint4
    const float4* wv = (const float4*)(w_of(sel) + (b << 11));
    float acc = 0.f;
#pragma unroll
    for (int it = 0; it < 8; it++) {
        uint4 h = hrow[it * 32 + lane];
        float4 wa = wv[(it * 32 + lane) * 2];
        float4 wb = wv[(it * 32 + lane) * 2 + 1];
        float2 h0 = __half22float2(*(const __half2*)&h.x);
        float2 h1 = __half22float2(*(const __half2*)&h.y);
        float2 h2 = __half22float2(*(const __half2*)&h.z);
        float2 h3 = __half22float2(*(const __half2*)&h.w);
        acc = fmaf(h0.x, wa.x, acc);
        acc = fmaf(h0.y, wa.y, acc);
        acc = fmaf(h1.x, wa.z, acc);
        acc = fmaf(h1.y, wa.w, acc);
        acc = fmaf(h2.x, wb.x, acc);
        acc = fmaf(h2.y, wb.y, acc);
        acc = fmaf(h3.x, wb.z, acc);
        acc = fmaf(h3.y, wb.w, acc);
    }
#pragma unroll
    for (int o = 16; o; o >>= 1) acc += __shfl_xor_sync(0xffffffffu, acc, o);
    if (lane == 0) {
        if (final_mode) {
            S_of(sel)[gw] = acc;
        } else {
            float* f = f_of(sel);
            f[gw] = 0.5f * f[gw] - 0.5f * __logf(acc);
        }
    }
}

// Column GEMV over g_Hyx: S2[b,l] += sum_k Hyx[b,k,l] * w2[b,k].
// grid (32 k-splits, 1, B); 256 threads; thread t owns 8 consecutive columns.
__global__ __launch_bounds__(256) void k_gemv_cols() {
    __shared__ float ws[64];
    int b = blockIdx.z, ks = blockIdx.x;
    int tid = threadIdx.x;
    if (tid < 64) ws[tid] = g_w2[b * NN + ks * 64 + tid];
    __syncthreads();

    const uint4* Hb = (const uint4*)(g_Hyx + ((size_t)b * NN + ks * 64) * NN);
    float acc[8];
#pragma unroll
    for (int j = 0; j < 8; j++) acc[j] = 0.f;
#pragma unroll 4
    for (int k = 0; k < 64; k++) {
        float wk = ws[k];
        uint4 h = Hb[(size_t)k * (NN / 8) + tid];
        float2 h0 = __half22float2(*(const __half2*)&h.x);
        float2 h1 = __half22float2(*(const __half2*)&h.y);
        float2 h2 = __half22float2(*(const __half2*)&h.z);
        float2 h3 = __half22float2(*(const __half2*)&h.w);
        acc[0] = fmaf(h0.x, wk, acc[0]);
        acc[1] = fmaf(h0.y, wk, acc[1]);
        acc[2] = fmaf(h1.x, wk, acc[2]);
        acc[3] = fmaf(h1.y, wk, acc[3]);
        acc[4] = fmaf(h2.x, wk, acc[4]);
        acc[5] = fmaf(h2.y, wk, acc[5]);
        acc[6] = fmaf(h3.x, wk, acc[6]);
        acc[7] = fmaf(h3.y, wk, acc[7]);
    }
    float* S = g_S2 + b * NN + 8 * tid;
#pragma unroll
    for (int j = 0; j < 8; j++) atomicAdd(S + j, acc[j]);
}

// res[b] = sum_l (fe_xy - fe_xx) * exp(a) + sum_k (fe_yx - fe_yy) * exp(b)
// with fe_* = -log(S_*). S0=xx, S1=yx, S2=xy, S3=yy.
__global__ __launch_bounds__(256) void k_reduce(const float* __restrict__ a,
                                                const float* __restrict__ bw,
                                                float* __restrict__ out) {
    int b = blockIdx.x;
    float acc = 0.f;
    for (int i = threadIdx.x; i < NN; i += 256) {
        int idx = b * NN + i;
        float fexx = -__logf(g_S0[idx]);
        float feyx = -__logf(g_S1[idx]);
        float fexy = -__logf(g_S2[idx]);
        float feyy = -__logf(g_S3[idx]);
        acc += (fexy - fexx) * __expf(a[idx]) + (feyx - feyy) * __expf(bw[idx]);
    }
    __shared__ float red[256];
    red[threadIdx.x] = acc;
    __syncthreads();
    for (int s = 128; s; s >>= 1) {
        if (threadIdx.x < s) red[threadIdx.x] += red[threadIdx.x + s];
        __syncthreads();
    }
    if (threadIdx.x == 0) out[b] = red[0];   // EPSILON = 1
}

// ---------------- launch ----------------
extern "C" void kernel_launch(void* const* d_in, const int* in_sizes, int n_in,
                              void* d_out, int out_size) {
    const float* x = (const float*)d_in[0];   // (8, 2048, 32)
    const float* a = (const float*)d_in[1];   // (8, 2048)
    const float* y = (const float*)d_in[2];   // (8, 2048, 32)
    const float* b = (const float*)d_in[3];   // (8, 2048)
    float* out = (float*)d_out;               // (8,)

    const int SMALL_BLOCKS = TOT / 256;           // 64
    const int ROW_BLOCKS = TOT / 8;               // one warp/row, 8 warps/block -> 2048
    dim3 buildGrid(NN / 64, NN / 64, BB);         // (32, 32, 8)
    dim3 colsGrid(32, 1, BB);                     // k-split 32, batch 8

    k_norms<<<SMALL_BLOCKS, 256>>>(x, y);

    k_build<<<buildGrid, 256>>>(0, x, x, 0, 0);   // Hxx
    k_build<<<buildGrid, 256>>>(1, y, x, 1, 0);   // Hyx (rows=y, cols=x)
    k_build<<<buildGrid, 256>>>(2, y, y, 1, 1);   // Hyy

    // Iterations 0..9 are Sinkhorn updates; iteration 10 is the final
    // differentiable extrapolation (same data flow, raw sums stored).
    for (int it = 0; it <= 10; it++) {
        int fin = (it == 10);
        // apply deferred fxy epilogue (from prev iter's col GEMV) + weights
        k_prep_all<<<SMALL_BLOCKS, 256>>>(a, b, it > 0);
        // independent updates first (Hxx, Hyy), then Hyx rows so Hyx is L2-hot
        // for the immediately following column GEMV.
        k_gemv_rows<<<dim3(ROW_BLOCKS, 2), 256>>>(0, 2, fin);  // fxx (Hxx), fyy (Hyy)
        k_gemv_rows<<<dim3(ROW_BLOCKS, 1), 256>>>(1, 1, fin);  // fyx (Hyx rows, old fxy)
        // fxy update needs NEW fyx
        k_prep2<<<SMALL_BLOCKS, 256>>>(b);
        k_gemv_cols<<<colsGrid, 256>>>();
        // fxy epilogue deferred to next k_prep_all (final iter: S2 stays raw)
    }

    k_reduce<<<BB, 256>>>(a, b, out);
}

// round 3
// speedup vs baseline: 1.9014x; 1.1531x over previous
#include <cuda_runtime.h>
#include <cuda_fp16.h>

// Problem constants (fixed by setup_inputs): B=8, L=K=2048, D=32, SIGMA=1, EPS=1, 10 iters.
#define BB 8
#define NN 2048
#define DD 32
#define TOT (BB * NN)
#define MAT_ELEMS ((size_t)BB * NN * NN)

// ---------------- device scratch (no runtime allocation allowed) ----------------
static __device__ __half g_Hxx[MAT_ELEMS];   // exp(gauss(x_l, x_k)) fp16 (symmetric)
static __device__ __half g_Hyx[MAT_ELEMS];   // exp(gauss(y_k, x_l)), rows = y index
static __device__ __half g_Hyy[MAT_ELEMS];   // exp(gauss(y_k, y_j)) fp16 (symmetric)
static __device__ float g_nx[TOT], g_ny[TOT];
static __device__ float g_fxx[TOT], g_fyx[TOT], g_fxy[TOT], g_fyy[TOT];
static __device__ float g_w0[TOT], g_w1[TOT], g_w3[TOT];
static __device__ float g_S0[TOT], g_S1[TOT], g_S2[TOT], g_S3[TOT];

// ---------------- kernels ----------------

// Squared norms of x and y rows + zero-init potentials and S2 accumulator.
__global__ __launch_bounds__(256) void k_norms(const float* __restrict__ x,
                                               const float* __restrict__ y) {
    int i = blockIdx.x * 256 + threadIdx.x;
    if (i >= TOT) return;
    const float* xr = x + (size_t)i * DD;
    const float* yr = y + (size_t)i * DD;
    float sx = 0.f, sy = 0.f;
#pragma unroll
    for (int d = 0; d < DD; d++) {
        sx = fmaf(xr[d], xr[d], sx);
        sy = fmaf(yr[d], yr[d], sy);
    }
    g_nx[i] = sx;
    g_ny[i] = sy;
    g_fxx[i] = 0.f; g_fyx[i] = 0.f; g_fxy[i] = 0.f; g_fyy[i] = 0.f;
}

// Build H[b][r][c] = exp( exp( -max(nr+nc-2*dot, 0)/2 ) ), stored fp16.
// 64x64 tile/block, 256 threads, 4x4 micro-tile. If sym!=0 only lower-triangle
// blocks compute; the mirror tile is written via an SMEM transpose (coalesced).
__global__ __launch_bounds__(256) void k_build(int hsel, int sym,
                                               const float* __restrict__ Rm,
                                               const float* __restrict__ Cm,
                                               int rn, int cn) {
    int bx = blockIdx.x, by = blockIdx.y, b = blockIdx.z;
    if (sym && bx > by) return;     // upper-triangle blocks filled by mirror
    __shared__ float srt[DD][68];
    __shared__ float sct[DD][68];
    __shared__ __half stile[64][72];  // for mirror transpose

    int r0 = by * 64, c0 = bx * 64;
    const float* Rb = Rm + ((size_t)b * NN + r0) * DD;
    const float* Cb = Cm + ((size_t)b * NN + c0) * DD;
    for (int i = threadIdx.x; i < 64 * DD; i += 256) {
        int row = i >> 5, d = i & 31;
        srt[d][row] = Rb[i];
        sct[d][row] = Cb[i];
    }
    __syncthreads();

    int tx = threadIdx.x & 15, ty = threadIdx.x >> 4;
    float acc[4][4];
#pragma unroll
    for (int i = 0; i < 4; i++)
#pragma unroll
        for (int j = 0; j < 4; j++) acc[i][j] = 0.f;

#pragma unroll
    for (int d = 0; d < DD; d++) {
        float4 rv4 = *(const float4*)&srt[d][ty * 4];
        float4 cv4 = *(const float4*)&sct[d][tx * 4];
        float rv[4] = {rv4.x, rv4.y, rv4.z, rv4.w};
        float cv[4] = {cv4.x, cv4.y, cv4.z, cv4.w};
#pragma unroll
        for (int i = 0; i < 4; i++)
#pragma unroll
            for (int j = 0; j < 4; j++)
                acc[i][j] = fmaf(rv[i], cv[j], acc[i][j]);
    }

    const float* nRp = (rn ? g_ny : g_nx) + b * NN + r0;
    const float* nCp = (cn ? g_ny : g_nx) + b * NN + c0;
    float nr[4], ncv[4];
#pragma unroll
    for (int i = 0; i < 4; i++) nr[i] = nRp[ty * 4 + i];
#pragma unroll
    for (int j = 0; j < 4; j++) ncv[j] = nCp[tx * 4 + j];

    __half* H = (hsel == 0 ? g_Hxx : hsel == 1 ? g_Hyx : g_Hyy);
    bool mirror = sym && (bx != by);
#pragma unroll
    for (int i = 0; i < 4; i++) {
        float o[4];
#pragma unroll
        for (int j = 0; j < 4; j++) {
            float dist = nr[i] + ncv[j] - 2.f * acc[i][j];
            float t = __expf(-0.5f * fmaxf(dist, 0.f));   // gauss value in (0,1]
            o[j] = __expf(t);                             // outer exp
        }
        union { __half2 h2[2]; uint2 u; } cv;
        cv.h2[0] = __floats2half2_rn(o[0], o[1]);
        cv.h2[1] = __floats2half2_rn(o[2], o[3]);
        *(uint2*)&H[((size_t)b * NN + r0 + ty * 4 + i) * NN + c0 + tx * 4] = cv.u;
        if (mirror) *(uint2*)&stile[ty * 4 + i][tx * 4] = cv.u;
    }
    if (mirror) {
        __syncthreads();
        // mirror tile: H[c0+row][r0+col] = stile[col][row]; coalesced uint2 writes
#pragma unroll
        for (int i = 0; i < 4; i++) {
            int mr = ty * 4 + i;          // row within mirror tile (= original col)
            __half v[4];
#pragma unroll
            for (int j = 0; j < 4; j++) v[j] = stile[tx * 4 + j][mr];
            *(uint2*)&H[((size_t)b * NN + c0 + mr) * NN + r0 + tx * 4] = *(uint2*)v;
        }
    }
}

// Per-iteration prep: apply deferred fxy epilogue (from previous iteration's
// column GEMV), zero S2 for the upcoming column GEMV, compute weight vectors.
__global__ __launch_bounds__(256) void k_prep_all(const float* __restrict__ a,
                                                  const float* __restrict__ bw,
                                                  int do_epi) {
    int i = blockIdx.x * 256 + threadIdx.x;
    if (i >= TOT) return;
    float fxy = g_fxy[i];
    if (do_epi) {
        fxy = 0.5f * fxy - 0.5f * __logf(g_S2[i]);
        g_fxy[i] = fxy;
    }
    g_S2[i] = 0.f;
    g_w0[i] = __expf(a[i] + g_fxx[i]);   // fxx update (Hxx rows)
    g_w1[i] = __expf(a[i] + fxy);        // fyx update (Hyx rows, OLD fxy)
    g_w3[i] = __expf(bw[i] + g_fyy[i]);  // fyy update (Hyy rows)
}

// Row GEMV over all three H matrices in one launch (blockIdx.y selects).
// 8 rows per block (one warp each); the 8 KB w vector is staged in SMEM once.
// final_mode=0: f = 0.5 f - 0.5 log(S).  final_mode=1: store raw S.
__global__ __launch_bounds__(256) void k_gemv_rows(int final_mode) {
    __shared__ float ws[NN];
    int sel = blockIdx.y;   // 0: Hxx/w0/fxx/S0, 1: Hyy/w3/fyy/S3, 2: Hyx/w1/fyx/S1
    const __half* H = sel == 0 ? g_Hxx : sel == 1 ? g_Hyy : g_Hyx;
    const float* w = sel == 0 ? g_w0 : sel == 1 ? g_w3 : g_w1;
    float* f = sel == 0 ? g_fxx : sel == 1 ? g_fyy : g_fyx;
    float* S = sel == 0 ? g_S0 : sel == 1 ? g_S3 : g_S1;

    int row0 = blockIdx.x * 8;
    int b = row0 >> 11;
    // stage w[b] into SMEM (float4 loads, 512 per block)
    const float4* wg = (const float4*)(w + (b << 11));
    float4* wsv = (float4*)ws;
#pragma unroll
    for (int i = 0; i < 2; i++) wsv[i * 256 + threadIdx.x] = wg[i * 256 + threadIdx.x];
    __syncthreads();

    int warp = threadIdx.x >> 5, lane = threadIdx.x & 31;
    int row = row0 + warp;
    const uint4* hrow = (const uint4*)(H + (size_t)row * NN);  // 8 halves per uint4
    float acc0 = 0.f, acc1 = 0.f;
#pragma unroll
    for (int it = 0; it < 8; it++) {
        uint4 h = hrow[it * 32 + lane];
        const float* wp = &ws[(it * 32 + lane) * 8];
        float4 wa = *(const float4*)wp;
        float4 wb = *(const float4*)(wp + 4);
        float2 h0 = __half22float2(*(const __half2*)&h.x);
        float2 h1 = __half22float2(*(const __half2*)&h.y);
        float2 h2 = __half22float2(*(const __half2*)&h.z);
        float2 h3 = __half22float2(*(const __half2*)&h.w);
        acc0 = fmaf(h0.x, wa.x, acc0);
        acc1 = fmaf(h0.y, wa.y, acc1);
        acc0 = fmaf(h1.x, wa.z, acc0);
        acc1 = fmaf(h1.y, wa.w, acc1);
        acc0 = fmaf(h2.x, wb.x, acc0);
        acc1 = fmaf(h2.y, wb.y, acc1);
        acc0 = fmaf(h3.x, wb.z, acc0);
        acc1 = fmaf(h3.y, wb.w, acc1);
    }
    float acc = acc0 + acc1;
#pragma unroll
    for (int o = 16; o; o >>= 1) acc += __shfl_xor_sync(0xffffffffu, acc, o);
    if (lane == 0) {
        if (final_mode) S[row] = acc;
        else            f[row] = 0.5f * f[row] - 0.5f * __logf(acc);
    }
}

// Column GEMV over g_Hyx: S2[b,l] += sum_k Hyx[b,k,l] * exp(b[k] + fyx[k]).
// w2 computed in-kernel (needs NEW fyx, guaranteed by launch order).
// grid (32 k-splits, 1, B); thread t owns 8 consecutive columns.
__global__ __launch_bounds__(256) void k_gemv_cols(const float* __restrict__ bw) {
    __shared__ float ws[64];
    int b = blockIdx.z, ks = blockIdx.x;
    int tid = threadIdx.x;
    if (tid < 64) {
        int k = b * NN + ks * 64 + tid;
        ws[tid] = __expf(bw[k] + g_fyx[k]);
    }
    __syncthreads();

    const uint4* Hb = (const uint4*)(g_Hyx + ((size_t)b * NN + ks * 64) * NN);
    float acc[8];
#pragma unroll
    for (int j = 0; j < 8; j++) acc[j] = 0.f;
#pragma unroll 4
    for (int k = 0; k < 64; k++) {
        float wk = ws[k];
        uint4 h = Hb[(size_t)k * (NN / 8) + tid];
        float2 h0 = __half22float2(*(const __half2*)&h.x);
        float2 h1 = __half22float2(*(const __half2*)&h.y);
        float2 h2 = __half22float2(*(const __half2*)&h.z);
        float2 h3 = __half22float2(*(const __half2*)&h.w);
        acc[0] = fmaf(h0.x, wk, acc[0]);
        acc[1] = fmaf(h0.y, wk, acc[1]);
        acc[2] = fmaf(h1.x, wk, acc[2]);
        acc[3] = fmaf(h1.y, wk, acc[3]);
        acc[4] = fmaf(h2.x, wk, acc[4]);
        acc[5] = fmaf(h2.y, wk, acc[5]);
        acc[6] = fmaf(h3.x, wk, acc[6]);
        acc[7] = fmaf(h3.y, wk, acc[7]);
    }
    float* S = g_S2 + b * NN + 8 * tid;
#pragma unroll
    for (int j = 0; j < 8; j++) atomicAdd(S + j, acc[j]);
}

// res[b] = sum_l (fe_xy - fe_xx) * exp(a) + sum_k (fe_yx - fe_yy) * exp(b)
// with fe_* = -log(S_*). S0=xx, S1=yx, S2=xy, S3=yy.
__global__ __launch_bounds__(256) void k_reduce(const float* __restrict__ a,
                                                const float* __restrict__ bw,
                                                float* __restrict__ out) {
    int b = blockIdx.x;
    float acc = 0.f;
    for (int i = threadIdx.x; i < NN; i += 256) {
        int idx = b * NN + i;
        float fexx = -__logf(g_S0[idx]);
        float feyx = -__logf(g_S1[idx]);
        float fexy = -__logf(g_S2[idx]);
        float feyy = -__logf(g_S3[idx]);
        acc += (fexy - fexx) * __expf(a[idx]) + (feyx - feyy) * __expf(bw[idx]);
    }
    __shared__ float red[256];
    red[threadIdx.x] = acc;
    __syncthreads();
    for (int s = 128; s; s >>= 1) {
        if (threadIdx.x < s) red[threadIdx.x] += red[threadIdx.x + s];
        __syncthreads();
    }
    if (threadIdx.x == 0) out[b] = red[0];   // EPSILON = 1
}

// ---------------- launch ----------------
extern "C" void kernel_launch(void* const* d_in, const int* in_sizes, int n_in,
                              void* d_out, int out_size) {
    const float* x = (const float*)d_in[0];   // (8, 2048, 32)
    const float* a = (const float*)d_in[1];   // (8, 2048)
    const float* y = (const float*)d_in[2];   // (8, 2048, 32)
    const float* b = (const float*)d_in[3];   // (8, 2048)
    float* out = (float*)d_out;               // (8,)

    const int SMALL_BLOCKS = TOT / 256;           // 64
    dim3 buildGrid(NN / 64, NN / 64, BB);         // (32, 32, 8)
    dim3 rowsGrid(TOT / 8, 3);                    // 2048 x 3 matrices
    dim3 colsGrid(32, 1, BB);                     // k-split 32, batch 8

    k_norms<<<SMALL_BLOCKS, 256>>>(x, y);

    k_build<<<buildGrid, 256>>>(0, 1, x, x, 0, 0);   // Hxx (symmetric)
    k_build<<<buildGrid, 256>>>(1, 0, y, x, 1, 0);   // Hyx (rows=y, cols=x)
    k_build<<<buildGrid, 256>>>(2, 1, y, y, 1, 1);   // Hyy (symmetric)

    // Iterations 0..9: Sinkhorn updates; iteration 10: final extrapolation.
    for (int it = 0; it <= 10; it++) {
        int fin = (it == 10);
        k_prep_all<<<SMALL_BLOCKS, 256>>>(a, b, it > 0);  // epilogue + weights + zero S2
        k_gemv_rows<<<rowsGrid, 256>>>(fin);              // fxx, fyy, fyx (independent)
        k_gemv_cols<<<colsGrid, 256>>>(b);                // fxy partial sums into S2
    }

    k_reduce<<<BB, 256>>>(a, b, out);
}